// round 2
// baseline (speedup 1.0000x reference)
#include <cuda_runtime.h>
#include <math.h>

// ---------------------------------------------------------------------------
// LoFTR linear attention, fp32 SIMT baseline.
//   B=8, L=8192, E=256, H=8, D=32, M = B*L = 65536
// Pipeline:
//   zero_kv  : clear KV/Ksum accumulators
//   proj_kv  : Q/K/V projections + feature map; Qf -> scratch; KV,Ksum atomically
//   msg_out  : Z + msg (Qf @ KV * Z) + output projection (@ Wm^T)
// ---------------------------------------------------------------------------

#define Bb 8
#define Ls 8192
#define Es 256
#define Hh 8
#define Dd 32
#define Mrows (Bb * Ls)

// scratch (static device allocations are allowed)
__device__ float g_Qf[(size_t)Mrows * Es];       // 64 MB
__device__ float g_KV[Bb * Hh * Dd * Dd];        // 65536 floats
__device__ float g_Ksum[Bb * Hh * Dd];           // 2048 floats

__device__ __forceinline__ float fmap(float x) {
    // elu(x)+1
    return x > 0.0f ? x + 1.0f : expf(x);
}

// ---------------------------------------------------------------------------
__global__ void zero_kv_kernel() {
    int i = blockIdx.x * blockDim.x + threadIdx.x;
    if (i < Bb * Hh * Dd * Dd) g_KV[i] = 0.0f;
    if (i < Bb * Hh * Dd)      g_Ksum[i] = 0.0f;
}

// ---------------------------------------------------------------------------
// Kernel 1: projections + feature map + KV/Ksum accumulation
//   block: 256 threads, row tile TM=128, N slab 64 (=2 heads), K step 16
// smem layout (floats):
//   sXT [16][132]   staging, X transposed      : 2112
//   sWT [16][68]    staging, W transposed      : 1088
//   sKf [128][66]   Kf slab                    : 8448
//   sVn [128][66]   V slab                     : 8448
// total 20096 floats = 80384 B
#define K1_SMEM_FLOATS 20096
#define K1_SMEM_BYTES  (K1_SMEM_FLOATS * 4)

__global__ __launch_bounds__(256)
void proj_kv_kernel(const float* __restrict__ q,
                    const float* __restrict__ kin,
                    const float* __restrict__ vin,
                    const float* __restrict__ Wq, const float* __restrict__ bq,
                    const float* __restrict__ Wk, const float* __restrict__ bk,
                    const float* __restrict__ Wv, const float* __restrict__ bv) {
    extern __shared__ float smem[];
    float* sXT = smem;                 // [16][132]
    float* sWT = smem + 2112;          // [16][68]
    float* sKf = smem + 3200;          // [128][66]
    float* sVn = smem + 11648;         // [128][66]

    const int tile = blockIdx.x;           // 0..511
    const int row0 = tile * 128;
    const int b    = row0 >> 13;           // row0 / 8192

    const int t  = threadIdx.x;
    const int ty = t >> 4;                 // 0..15 (8 rows each)
    const int tx = t & 15;                 // 0..15 (4 cols each)

    for (int nt = 0; nt < 4; ++nt) {
        const int n0 = nt * 64;

        for (int mat = 0; mat < 3; ++mat) {
            const float* X  = (mat == 0) ? q  : (mat == 1) ? kin : vin;
            const float* W  = (mat == 0) ? Wq : (mat == 1) ? Wk  : Wv;
            const float* bi = (mat == 0) ? bq : (mat == 1) ? bk  : bv;

            float acc[8][4];
#pragma unroll
            for (int i = 0; i < 8; ++i)
#pragma unroll
                for (int j = 0; j < 4; ++j) acc[i][j] = 0.0f;

            for (int k0 = 0; k0 < Es; k0 += 16) {
                __syncthreads();
                // stage X tile [128 x 16] transposed
#pragma unroll
                for (int s = t; s < 512; s += 256) {
                    int r  = s >> 2;
                    int c4 = (s & 3) << 2;
                    float4 xv = *(const float4*)(X + (size_t)(row0 + r) * Es + k0 + c4);
                    sXT[(c4 + 0) * 132 + r] = xv.x;
                    sXT[(c4 + 1) * 132 + r] = xv.y;
                    sXT[(c4 + 2) * 132 + r] = xv.z;
                    sXT[(c4 + 3) * 132 + r] = xv.w;
                }
                // stage W tile [64 x 16] transposed
                {
                    int n  = t >> 2;
                    int c4 = (t & 3) << 2;
                    float4 wv = *(const float4*)(W + (size_t)(n0 + n) * Es + k0 + c4);
                    sWT[(c4 + 0) * 68 + n] = wv.x;
                    sWT[(c4 + 1) * 68 + n] = wv.y;
                    sWT[(c4 + 2) * 68 + n] = wv.z;
                    sWT[(c4 + 3) * 68 + n] = wv.w;
                }
                __syncthreads();
#pragma unroll
                for (int kk = 0; kk < 16; ++kk) {
                    float4 a0 = *(const float4*)&sXT[kk * 132 + ty * 8];
                    float4 a1 = *(const float4*)&sXT[kk * 132 + ty * 8 + 4];
                    float4 b0 = *(const float4*)&sWT[kk * 68 + tx * 4];
                    float a[8] = {a0.x, a0.y, a0.z, a0.w, a1.x, a1.y, a1.z, a1.w};
                    float bb[4] = {b0.x, b0.y, b0.z, b0.w};
#pragma unroll
                    for (int i = 0; i < 8; ++i)
#pragma unroll
                        for (int j = 0; j < 4; ++j)
                            acc[i][j] += a[i] * bb[j];
                }
            }

            // epilogue
            float4 bias4 = *(const float4*)(bi + n0 + tx * 4);
            float bb[4] = {bias4.x, bias4.y, bias4.z, bias4.w};

            if (mat == 0) {
#pragma unroll
                for (int i = 0; i < 8; ++i) {
                    float4 o;
                    o.x = fmap(acc[i][0] + bb[0]);
                    o.y = fmap(acc[i][1] + bb[1]);
                    o.z = fmap(acc[i][2] + bb[2]);
                    o.w = fmap(acc[i][3] + bb[3]);
                    *(float4*)(g_Qf + (size_t)(row0 + ty * 8 + i) * Es + n0 + tx * 4) = o;
                }
            } else if (mat == 1) {
#pragma unroll
                for (int i = 0; i < 8; ++i)
#pragma unroll
                    for (int j = 0; j < 4; ++j)
                        sKf[(ty * 8 + i) * 66 + tx * 4 + j] = fmap(acc[i][j] + bb[j]);
            } else {
#pragma unroll
                for (int i = 0; i < 8; ++i)
#pragma unroll
                    for (int j = 0; j < 4; ++j)
                        sVn[(ty * 8 + i) * 66 + tx * 4 + j] = acc[i][j] + bb[j];
            }
        }

        __syncthreads();
        // KV accumulation for the two heads in this slab: 2*32*32 = 2048 outputs
        for (int o = t; o < 2048; o += 256) {
            int hh = o >> 10;            // head within slab
            int d  = (o >> 5) & 31;
            int e  = o & 31;
            int ck = hh * 32 + d;
            int cv = hh * 32 + e;
            float accKV = 0.0f;
#pragma unroll 4
            for (int r = 0; r < 128; ++r)
                accKV += sKf[r * 66 + ck] * sVn[r * 66 + cv];
            int hg = nt * 2 + hh;
            atomicAdd(&g_KV[((b * Hh + hg) * Dd + d) * Dd + e], accKV);
        }
        // Ksum for the 64 columns of this slab
        if (t < 64) {
            float s = 0.0f;
#pragma unroll 4
            for (int r = 0; r < 128; ++r) s += sKf[r * 66 + t];
            int hg = nt * 2 + (t >> 5);
            int d  = t & 31;
            atomicAdd(&g_Ksum[(b * Hh + hg) * Dd + d], s);
        }
        __syncthreads();
    }
}

// ---------------------------------------------------------------------------
// Kernel 2: Z + msg + output projection
//   block: 256 threads, row tile 64
// smem layout (floats):
//   sQf  [64][260]  : 16640
//   sMsg [64][260]  : 16640
//   sKV  [8192]     : 8192
//   sKsum[256]      : 256
//   sZ   [512]      : 512
//   sWT2 [16][68]   : 1088
// total 43328 floats = 173312 B
#define K2_SMEM_FLOATS 43328
#define K2_SMEM_BYTES  (K2_SMEM_FLOATS * 4)

__global__ __launch_bounds__(256)
void msg_out_kernel(const float* __restrict__ Wm, float* __restrict__ out) {
    extern __shared__ float smem[];
    float* sQf   = smem;            // [64][260]
    float* sMsg  = smem + 16640;    // [64][260]
    float* sKV   = smem + 33280;    // [8][32][32]
    float* sKsum = smem + 41472;    // [256]
    float* sZ    = smem + 41728;    // [64][8]
    float* sWT2  = smem + 42240;    // [16][68]

    const int tile = blockIdx.x;        // 0..1023
    const int row0 = tile * 64;
    const int b    = row0 >> 13;

    const int t = threadIdx.x;

    // Phase A: load Qf tile, KV, Ksum
    const float* Qfb = g_Qf + (size_t)row0 * Es;
    for (int s = t; s < 64 * 64; s += 256) {
        int r  = s >> 6;
        int c4 = (s & 63) << 2;
        float4 v4 = *(const float4*)(Qfb + r * Es + c4);
        *(float4*)&sQf[r * 260 + c4] = v4;
    }
    for (int s = t; s < 2048; s += 256) {
        float4 v4 = *(const float4*)(g_KV + b * 8192 + s * 4);
        *(float4*)&sKV[s * 4] = v4;
    }
    if (t < 64) {
        float4 v4 = *(const float4*)(g_Ksum + b * 256 + t * 4);
        *(float4*)&sKsum[t * 4] = v4;
    }
    __syncthreads();

    // Phase B: Z = 1 / (Qf . Ksum + eps)
    for (int task = t; task < 512; task += 256) {
        int r = task >> 3;
        int h = task & 7;
        float dot = 0.0f;
#pragma unroll
        for (int d = 0; d < 32; ++d)
            dot += sQf[r * 260 + h * 32 + d] * sKsum[h * 32 + d];
        sZ[r * 8 + h] = 1.0f / (dot + 1e-6f);
    }
    __syncthreads();

    // Phase C: msg[r][c] = Z * sum_d Qf[r][h*32+d] * KV[h][d][e], c = t
    {
        int h = t >> 5;
        int e = t & 31;
        float kvreg[32];
#pragma unroll
        for (int d = 0; d < 32; ++d) kvreg[d] = sKV[h * 1024 + d * 32 + e];
        for (int r = 0; r < 64; ++r) {
            float a = 0.0f;
#pragma unroll
            for (int d4 = 0; d4 < 8; ++d4) {
                float4 qv = *(const float4*)&sQf[r * 260 + h * 32 + d4 * 4];
                a += qv.x * kvreg[d4 * 4 + 0];
                a += qv.y * kvreg[d4 * 4 + 1];
                a += qv.z * kvreg[d4 * 4 + 2];
                a += qv.w * kvreg[d4 * 4 + 3];
            }
            sMsg[r * 260 + t] = a * sZ[r * 8 + h];
        }
    }
    __syncthreads();

    // Phase D: out tile = sMsg @ Wm^T   (64x256 @ 256x256)
    const int ty = t >> 4;   // 0..15, 4 rows each
    const int tx = t & 15;   // 0..15, 4 cols each
    for (int nt = 0; nt < 4; ++nt) {
        const int n0 = nt * 64;
        float acc[4][4];
#pragma unroll
        for (int i = 0; i < 4; ++i)
#pragma unroll
            for (int j = 0; j < 4; ++j) acc[i][j] = 0.0f;

        for (int k0 = 0; k0 < Es; k0 += 16) {
            __syncthreads();
            {
                int n  = t >> 2;
                int c4 = (t & 3) << 2;
                float4 wv = *(const float4*)(Wm + (size_t)(n0 + n) * Es + k0 + c4);
                sWT2[(c4 + 0) * 68 + n] = wv.x;
                sWT2[(c4 + 1) * 68 + n] = wv.y;
                sWT2[(c4 + 2) * 68 + n] = wv.z;
                sWT2[(c4 + 3) * 68 + n] = wv.w;
            }
            __syncthreads();
#pragma unroll
            for (int kk = 0; kk < 16; ++kk) {
                float4 b0 = *(const float4*)&sWT2[kk * 68 + tx * 4];
                float bb[4] = {b0.x, b0.y, b0.z, b0.w};
                float a0 = sMsg[(ty * 4 + 0) * 260 + k0 + kk];
                float a1 = sMsg[(ty * 4 + 1) * 260 + k0 + kk];
                float a2 = sMsg[(ty * 4 + 2) * 260 + k0 + kk];
                float a3 = sMsg[(ty * 4 + 3) * 260 + k0 + kk];
                float a[4] = {a0, a1, a2, a3};
#pragma unroll
                for (int i = 0; i < 4; ++i)
#pragma unroll
                    for (int j = 0; j < 4; ++j)
                        acc[i][j] += a[i] * bb[j];
            }
        }
#pragma unroll
        for (int i = 0; i < 4; ++i) {
            float4 o = {acc[i][0], acc[i][1], acc[i][2], acc[i][3]};
            *(float4*)(out + (size_t)(row0 + ty * 4 + i) * Es + n0 + tx * 4) = o;
        }
    }
}

// ---------------------------------------------------------------------------
extern "C" void kernel_launch(void* const* d_in, const int* in_sizes, int n_in,
                              void* d_out, int out_size) {
    const float* q  = (const float*)d_in[0];
    const float* k  = (const float*)d_in[1];
    const float* v  = (const float*)d_in[2];
    const float* Wq = (const float*)d_in[3];
    const float* bq = (const float*)d_in[4];
    const float* Wk = (const float*)d_in[5];
    const float* bk = (const float*)d_in[6];
    const float* Wv = (const float*)d_in[7];
    const float* bv = (const float*)d_in[8];
    const float* Wm = (const float*)d_in[9];
    float* out = (float*)d_out;

    cudaFuncSetAttribute(proj_kv_kernel,
                         cudaFuncAttributeMaxDynamicSharedMemorySize, K1_SMEM_BYTES);
    cudaFuncSetAttribute(msg_out_kernel,
                         cudaFuncAttributeMaxDynamicSharedMemorySize, K2_SMEM_BYTES);

    zero_kv_kernel<<<(Bb * Hh * Dd * Dd + 255) / 256, 256>>>();
    proj_kv_kernel<<<Mrows / 128, 256, K1_SMEM_BYTES>>>(q, k, v, Wq, bq, Wk, bk, Wv, bv);
    msg_out_kernel<<<Mrows / 64, 256, K2_SMEM_BYTES>>>(Wm, out);
}